// round 12
// baseline (speedup 1.0000x reference)
#include <cuda_runtime.h>
#include <cuda_bf16.h>
#include <math.h>

// Problem constants: B=8, N=8192, C=256, K=8, nblocks=8, blk=32
#define TOK_TOTAL 65536          // B*N
#define N_TOK     8192
#define C_DIM     256
#define K_NB      8
#define EPS_W     0.05f
#define OME_W     0.95f

// Scratch (allocation-free rule: __device__ globals)
__device__ float          g_s1[(size_t)TOK_TOTAL * C_DIM];  // 64 MB rectify1 out (f32)
__device__ float          g_t [(size_t)TOK_TOTAL * C_DIM];  // 64 MB monarch out (f32)
__device__ __nv_bfloat16  g_th[(size_t)TOK_TOTAL * C_DIM];  // 32 MB bf16 shadow of t
__device__ __nv_bfloat16  g_xh[(size_t)TOK_TOTAL * C_DIM];  // 32 MB bf16 shadow of x
__device__ float          g_w [(size_t)TOK_TOTAL * K_NB];   // eps-scaled softmax weights

// bf16 -> f32 is exact: shift/mask into high mantissa bits (ALU pipe).
__device__ __forceinline__ float bf_lo(unsigned u) { return __uint_as_float(u << 16); }
__device__ __forceinline__ float bf_hi(unsigned u) { return __uint_as_float(u & 0xFFFF0000u); }

// ---- packed f32x2 helpers (FFMA2 is PTX-only; ptxas never auto-fuses) ------
union F2U { float2 f; unsigned long long u; };
__device__ __forceinline__ unsigned long long pk2(float x, float y) {
    F2U t; t.f.x = x; t.f.y = y; return t.u;
}
__device__ __forceinline__ void ffma2(unsigned long long& d,
                                      unsigned long long a,
                                      unsigned long long b) {
    asm("fma.rn.f32x2 %0, %1, %2, %0;" : "+l"(d) : "l"(a), "l"(b));
}
__device__ __forceinline__ float hsum2(unsigned long long v) {
    F2U t; t.u = v; return t.f.x + t.f.y;
}

// ---------------------------------------------------------------------------
// Kernel 0 (prep): blocks [0,256) compute eps*softmax(-distance);
// blocks [256, 256+16384) convert x (f32) -> g_xh (bf16).
// ---------------------------------------------------------------------------
__global__ void prep_k(const float* __restrict__ dist, const float* __restrict__ x) {
    if (blockIdx.x < 256) {
        int tok = blockIdx.x * blockDim.x + threadIdx.x;
        const float4* dp = (const float4*)(dist + (size_t)tok * K_NB);
        float4 a = dp[0], b4 = dp[1];
        float d[8] = {a.x, a.y, a.z, a.w, b4.x, b4.y, b4.z, b4.w};
        float e[8];
        float s = 0.f;
#pragma unroll
        for (int k = 0; k < 8; k++) { e[k] = __expf(-d[k]); s += e[k]; }
        float inv = EPS_W / s;
        float4* wp = (float4*)(g_w + (size_t)tok * K_NB);
        wp[0] = make_float4(e[0]*inv, e[1]*inv, e[2]*inv, e[3]*inv);
        wp[1] = make_float4(e[4]*inv, e[5]*inv, e[6]*inv, e[7]*inv);
    } else {
        size_t i = (size_t)(blockIdx.x - 256) * blockDim.x + threadIdx.x; // float4 id
        float4 f = __ldcs(&((const float4*)x)[i]);
        __nv_bfloat162 h0 = __float22bfloat162_rn(make_float2(f.x, f.y));
        __nv_bfloat162 h1 = __float22bfloat162_rn(make_float2(f.z, f.w));
        uint2 o;
        o.x = *reinterpret_cast<unsigned*>(&h0);
        o.y = *reinterpret_cast<unsigned*>(&h1);
        ((uint2*)g_xh)[i] = o;
    }
}

// ---------------------------------------------------------------------------
// Kernel 1a: rectify1, warp-per-token, barrier-free (k2 pattern).
// self from x (f32, streaming), neighbors from g_xh (bf16), writes s1 (f32).
// ---------------------------------------------------------------------------
__global__ void __launch_bounds__(256) rect1_k(
        const float* __restrict__ x,
        const int*   __restrict__ idx) {
    const int lane = threadIdx.x & 31;
    const int warp = threadIdx.x >> 5;
    const int tok  = blockIdx.x * 8 + warp;     // grid = TOK_TOTAL/8
    const int b    = tok >> 13;
    const __nv_bfloat16* xb = g_xh + ((size_t)b << 13) * C_DIM;

    float wv = 0.f; int iv = 0;
    if (lane < 8) {
        wv = g_w[(size_t)tok * 8 + lane];
        iv = idx[(size_t)tok * 8 + lane];
    }

    const float4* srow = (const float4*)(x + (size_t)tok * C_DIM);
    float4 s0 = __ldcs(&srow[2*lane]), s1 = __ldcs(&srow[2*lane + 1]);

    float4 a0 = make_float4(OME_W*s0.x, OME_W*s0.y, OME_W*s0.z, OME_W*s0.w);
    float4 a1 = make_float4(OME_W*s1.x, OME_W*s1.y, OME_W*s1.z, OME_W*s1.w);

#pragma unroll
    for (int k = 0; k < 8; k++) {
        float wk = __shfl_sync(0xFFFFFFFFu, wv, k);
        int   nb = __shfl_sync(0xFFFFFFFFu, iv, k);
        uint4 n = ((const uint4*)(xb + (size_t)nb * C_DIM))[lane];
        a0.x = fmaf(wk, bf_lo(n.x), a0.x);  a0.y = fmaf(wk, bf_hi(n.x), a0.y);
        a0.z = fmaf(wk, bf_lo(n.y), a0.z);  a0.w = fmaf(wk, bf_hi(n.y), a0.w);
        a1.x = fmaf(wk, bf_lo(n.z), a1.x);  a1.y = fmaf(wk, bf_hi(n.z), a1.y);
        a1.z = fmaf(wk, bf_lo(n.w), a1.z);  a1.w = fmaf(wk, bf_hi(n.w), a1.w);
    }

    float4* orow = (float4*)(g_s1 + (size_t)tok * C_DIM);
    __stcs(&orow[2*lane],     a0);     // read-once stream (monarch_k)
    __stcs(&orow[2*lane + 1], a1);
}

// ---------------------------------------------------------------------------
// Kernel 1b: monarch butterfly, pure streaming (no gathers, no random
// latency). 256 threads, 4 tokens/round, 8 rounds/block (2048 blocks).
// Prefetch = ONE coalesced LDG.128 per thread per round, double-buffered smem;
// f32x2 packed math in both stages.
// ---------------------------------------------------------------------------
__global__ void __launch_bounds__(256, 2) monarch_k(
        const float* __restrict__ w1,
        const float* __restrict__ w2,
        const float* __restrict__ bias) {
    __shared__ __align__(16) float sv[2][4][C_DIM];
    __shared__ __align__(16) float so1[4][288];     // 8 * 36 padded

    const int tid = threadIdx.x;

    // Per-thread monarch weight rows, pre-packed as f32x2 along the
    // reduction dimension (p for stage1, r for stage2).
    unsigned long long w1p[16], w2p[16];
    {
        const float4* p1 = (const float4*)(w1 + (size_t)tid * 32);
#pragma unroll
        for (int i = 0; i < 8; i++) {
            float4 f = p1[i];
            w1p[2*i+0] = pk2(f.x, f.y);
            w1p[2*i+1] = pk2(f.z, f.w);
        }
        const float4* p2 = (const float4*)(w2 + (size_t)(tid & 7) * 1024 + (size_t)(tid >> 3) * 32);
#pragma unroll
        for (int i = 0; i < 8; i++) {
            float4 f = p2[i];
            w2p[2*i+0] = pk2(f.x, f.y);
            w2p[2*i+1] = pk2(f.z, f.w);
        }
    }
    const unsigned long long brp = pk2(bias[tid], 0.f);

    const int t = tid >> 6;          // token-in-round 0..3
    const int q = tid & 63;          // float4 quad 0..63
    const int tokBlock = blockIdx.x * 32;            // 32 tokens per block

    const int kbase = tid & 0xE0;                    // stage1 input block base
    const int widx  = (tid & 7) * 36 + (tid >> 3);   // transposed o1 slot
    const int lbase = (tid & 7) * 36;                // stage2 input row base

    // ---- Prefetch round 0: one coalesced float4 per thread
    float4 pf = __ldcs(&((const float4*)(g_s1 + (size_t)(tokBlock + t) * C_DIM))[q]);

#pragma unroll 1
    for (int r = 0; r < 8; r++) {
        const int buf  = r & 1;
        const int tok0 = tokBlock + r * 4;

        // ---- Stage prefetched tile to smem; issue next round's prefetch
        ((float4*)sv[buf][t])[q] = pf;
        if (r < 7)
            pf = __ldcs(&((const float4*)(g_s1 + (size_t)(tok0 + 4 + t) * C_DIM))[q]);

        __syncthreads();   // sv[buf] visible; C(r-1) done reading so1

        // ---- Phase B: stage1, f32x2 along p. o1[k*32+q] = sum_p w1[k,q,p]*v
#pragma unroll
        for (int tt = 0; tt < 4; tt++) {
            const ulonglong2* vp = (const ulonglong2*)(&sv[buf][tt][kbase]);
            unsigned long long acc = 0ull;
#pragma unroll
            for (int p = 0; p < 8; p++) {
                ulonglong2 f = vp[p];          // LDS.128, pair-aliased
                ffma2(acc, w1p[2*p+0], f.x);
                ffma2(acc, w1p[2*p+1], f.y);
            }
            so1[tt][widx] = hsum2(acc);   // transposed: f=tid -> (l=f&7, r=f>>3)
        }
        __syncthreads();

        // ---- Phase C: stage2 + bias, f32x2 along r; write f32 t + bf16 shadow
#pragma unroll
        for (int tt = 0; tt < 4; tt++) {
            const ulonglong2* op = (const ulonglong2*)(&so1[tt][lbase]);
            unsigned long long acc = brp;
#pragma unroll
            for (int p = 0; p < 8; p++) {
                ulonglong2 f = op[p];
                ffma2(acc, w2p[2*p+0], f.x);
                ffma2(acc, w2p[2*p+1], f.y);
            }
            const float r2 = hsum2(acc);
            const size_t oi = (size_t)(tok0 + tt) * C_DIM + tid;
            __stcs(&g_t[oi], r2);                      // read-once stream
            g_th[oi] = __float2bfloat16_rn(r2);        // keep resident (gathered)
        }
        // no trailing barrier: next round's sv store targets the other buffer,
        // and barrier1 of the next round protects so1 against its next writer.
    }
}

// ---------------------------------------------------------------------------
// Kernel 2: rectify2 on t + rf. Warp-per-token, barrier-free, bf16 gathers.
// Streams (t self, rf, out) use evict-first hints so g_th stays L2-resident.
// ---------------------------------------------------------------------------
__global__ void __launch_bounds__(256) k2_rect_add(
        const float* __restrict__ rf,
        const int*   __restrict__ idx,
        float*       __restrict__ out) {
    const int lane = threadIdx.x & 31;
    const int warp = threadIdx.x >> 5;
    const int tok  = blockIdx.x * 8 + warp;     // grid = TOK_TOTAL/8
    const int b    = tok >> 13;
    const __nv_bfloat16* tb = g_th + ((size_t)b << 13) * C_DIM;

    float wv = 0.f; int iv = 0;
    if (lane < 8) {
        wv = g_w[(size_t)tok * 8 + lane];
        iv = idx[(size_t)tok * 8 + lane];
    }

    const float4* trow = (const float4*)(g_t + (size_t)tok * C_DIM);
    float4 s0 = __ldcs(&trow[2*lane]), s1 = __ldcs(&trow[2*lane + 1]);
    const float4* rrow = (const float4*)(rf + (size_t)tok * C_DIM);
    float4 r0 = __ldcs(&rrow[2*lane]), r1 = __ldcs(&rrow[2*lane + 1]);

    float4 a0 = make_float4(OME_W*s0.x + r0.x, OME_W*s0.y + r0.y,
                            OME_W*s0.z + r0.z, OME_W*s0.w + r0.w);
    float4 a1 = make_float4(OME_W*s1.x + r1.x, OME_W*s1.y + r1.y,
                            OME_W*s1.z + r1.z, OME_W*s1.w + r1.w);

#pragma unroll
    for (int k = 0; k < 8; k++) {
        float wk = __shfl_sync(0xFFFFFFFFu, wv, k);
        int   nb = __shfl_sync(0xFFFFFFFFu, iv, k);
        uint4 n = ((const uint4*)(tb + (size_t)nb * C_DIM))[lane];
        a0.x = fmaf(wk, bf_lo(n.x), a0.x);  a0.y = fmaf(wk, bf_hi(n.x), a0.y);
        a0.z = fmaf(wk, bf_lo(n.y), a0.z);  a0.w = fmaf(wk, bf_hi(n.y), a0.w);
        a1.x = fmaf(wk, bf_lo(n.z), a1.x);  a1.y = fmaf(wk, bf_hi(n.z), a1.y);
        a1.z = fmaf(wk, bf_lo(n.w), a1.z);  a1.w = fmaf(wk, bf_hi(n.w), a1.w);
    }

    float4* orow = (float4*)(out + (size_t)tok * C_DIM);
    __stcs(&orow[2*lane],     a0);
    __stcs(&orow[2*lane + 1], a1);
}

// ---------------------------------------------------------------------------
extern "C" void kernel_launch(void* const* d_in, const int* in_sizes, int n_in,
                              void* d_out, int out_size) {
    const float* x    = (const float*)d_in[0];
    const float* dist = (const float*)d_in[1];
    const int*   idx  = (const int*)  d_in[2];
    const float* rf   = (const float*)d_in[3];
    const float* w1   = (const float*)d_in[4];
    const float* w2   = (const float*)d_in[5];
    const float* bias = (const float*)d_in[6];
    float* out = (float*)d_out;

    prep_k<<<256 + (TOK_TOTAL * C_DIM / 4) / 256, 256>>>(dist, x);
    rect1_k<<<TOK_TOTAL / 8, 256>>>(x, idx);
    monarch_k<<<TOK_TOTAL / 32, 256>>>(w1, w2, bias);
    k2_rect_add<<<TOK_TOTAL / 8, 256>>>(rf, idx, out);
}

// round 13
// speedup vs baseline: 1.0138x; 1.0138x over previous
#include <cuda_runtime.h>
#include <cuda_bf16.h>
#include <math.h>

// Problem constants: B=8, N=8192, C=256, K=8, nblocks=8, blk=32
#define TOK_TOTAL 65536          // B*N
#define N_TOK     8192
#define C_DIM     256
#define K_NB      8
#define EPS_W     0.05f
#define OME_W     0.95f

// Scratch (allocation-free rule: __device__ globals)
__device__ float          g_s1[(size_t)TOK_TOTAL * C_DIM];  // 64 MB rectify1 out (f32)
__device__ float          g_t [(size_t)TOK_TOTAL * C_DIM];  // 64 MB monarch out (f32)
__device__ __nv_bfloat16  g_th[(size_t)TOK_TOTAL * C_DIM];  // 32 MB bf16 shadow of t
__device__ __nv_bfloat16  g_xh[(size_t)TOK_TOTAL * C_DIM];  // 32 MB bf16 shadow of x
__device__ float          g_w [(size_t)TOK_TOTAL * K_NB];   // eps-scaled softmax weights

// bf16 -> f32 is exact: shift/mask into high mantissa bits (ALU pipe).
__device__ __forceinline__ float bf_lo(unsigned u) { return __uint_as_float(u << 16); }
__device__ __forceinline__ float bf_hi(unsigned u) { return __uint_as_float(u & 0xFFFF0000u); }

// ---- packed f32x2 helpers (FFMA2 is PTX-only; ptxas never auto-fuses) ------
union F2U { float2 f; unsigned long long u; };
__device__ __forceinline__ unsigned long long pk2(float x, float y) {
    F2U t; t.f.x = x; t.f.y = y; return t.u;
}
__device__ __forceinline__ void ffma2(unsigned long long& d,
                                      unsigned long long a,
                                      unsigned long long b) {
    asm("fma.rn.f32x2 %0, %1, %2, %0;" : "+l"(d) : "l"(a), "l"(b));
}
__device__ __forceinline__ float hsum2(unsigned long long v) {
    F2U t; t.u = v; return t.f.x + t.f.y;
}

// ---------------------------------------------------------------------------
// Kernel 0 (prep): blocks [0,256) compute eps*softmax(-distance);
// blocks [256, 256+16384) convert x (f32) -> g_xh (bf16).
// ---------------------------------------------------------------------------
__global__ void prep_k(const float* __restrict__ dist, const float* __restrict__ x) {
    if (blockIdx.x < 256) {
        int tok = blockIdx.x * blockDim.x + threadIdx.x;
        const float4* dp = (const float4*)(dist + (size_t)tok * K_NB);
        float4 a = dp[0], b4 = dp[1];
        float d[8] = {a.x, a.y, a.z, a.w, b4.x, b4.y, b4.z, b4.w};
        float e[8];
        float s = 0.f;
#pragma unroll
        for (int k = 0; k < 8; k++) { e[k] = __expf(-d[k]); s += e[k]; }
        float inv = EPS_W / s;
        float4* wp = (float4*)(g_w + (size_t)tok * K_NB);
        wp[0] = make_float4(e[0]*inv, e[1]*inv, e[2]*inv, e[3]*inv);
        wp[1] = make_float4(e[4]*inv, e[5]*inv, e[6]*inv, e[7]*inv);
    } else {
        size_t i = (size_t)(blockIdx.x - 256) * blockDim.x + threadIdx.x; // float4 id
        float4 f = __ldcs(&((const float4*)x)[i]);
        __nv_bfloat162 h0 = __float22bfloat162_rn(make_float2(f.x, f.y));
        __nv_bfloat162 h1 = __float22bfloat162_rn(make_float2(f.z, f.w));
        uint2 o;
        o.x = *reinterpret_cast<unsigned*>(&h0);
        o.y = *reinterpret_cast<unsigned*>(&h1);
        ((uint2*)g_xh)[i] = o;
    }
}

// ---------------------------------------------------------------------------
// Kernel 1a: rectify1, warp-per-token, barrier-free, BATCHED gathers:
// all 8 neighbor LDG.128 issued back-to-back before any FMA (MLP_p1 = 8+).
// ---------------------------------------------------------------------------
__global__ void __launch_bounds__(256) rect1_k(
        const float* __restrict__ x,
        const int*   __restrict__ idx) {
    const int lane = threadIdx.x & 31;
    const int warp = threadIdx.x >> 5;
    const int tok  = blockIdx.x * 8 + warp;     // grid = TOK_TOTAL/8
    const int b    = tok >> 13;
    const __nv_bfloat16* xb = g_xh + ((size_t)b << 13) * C_DIM;

    float wv = 0.f; int iv = 0;
    if (lane < 8) {
        wv = g_w[(size_t)tok * 8 + lane];
        iv = idx[(size_t)tok * 8 + lane];
    }
    float wks[8]; const __nv_bfloat16* nps[8];
#pragma unroll
    for (int k = 0; k < 8; k++) {
        wks[k] = __shfl_sync(0xFFFFFFFFu, wv, k);
        nps[k] = xb + (size_t)__shfl_sync(0xFFFFFFFFu, iv, k) * C_DIM;
    }

    // batch all independent loads first
    const float4* srow = (const float4*)(x + (size_t)tok * C_DIM);
    float4 s0 = __ldcs(&srow[2*lane]), s1 = __ldcs(&srow[2*lane + 1]);
    uint4 nv[8];
#pragma unroll
    for (int k = 0; k < 8; k++) nv[k] = ((const uint4*)nps[k])[lane];

    float4 a0 = make_float4(OME_W*s0.x, OME_W*s0.y, OME_W*s0.z, OME_W*s0.w);
    float4 a1 = make_float4(OME_W*s1.x, OME_W*s1.y, OME_W*s1.z, OME_W*s1.w);
#pragma unroll
    for (int k = 0; k < 8; k++) {
        float wk = wks[k]; uint4 n = nv[k];
        a0.x = fmaf(wk, bf_lo(n.x), a0.x);  a0.y = fmaf(wk, bf_hi(n.x), a0.y);
        a0.z = fmaf(wk, bf_lo(n.y), a0.z);  a0.w = fmaf(wk, bf_hi(n.y), a0.w);
        a1.x = fmaf(wk, bf_lo(n.z), a1.x);  a1.y = fmaf(wk, bf_hi(n.z), a1.y);
        a1.z = fmaf(wk, bf_lo(n.w), a1.z);  a1.w = fmaf(wk, bf_hi(n.w), a1.w);
    }

    float4* orow = (float4*)(g_s1 + (size_t)tok * C_DIM);
    __stcs(&orow[2*lane],     a0);     // read-once stream (monarch_k)
    __stcs(&orow[2*lane + 1], a1);
}

// ---------------------------------------------------------------------------
// Kernel 1b: monarch butterfly, streaming, 8 tokens per round (4 rounds per
// block => 8 barriers instead of 16: bigger work quantum per barrier).
// f32x2 packed math; 8 independent accumulator chains per phase for ILP.
// ---------------------------------------------------------------------------
__global__ void __launch_bounds__(256, 2) monarch_k(
        const float* __restrict__ w1,
        const float* __restrict__ w2,
        const float* __restrict__ bias) {
    __shared__ __align__(16) float sv[2][8][C_DIM];   // 16 KB
    __shared__ __align__(16) float so1[8][288];       // 9 KB (8*36 padded rows)

    const int tid = threadIdx.x;

    // Per-thread monarch weight rows, pre-packed as f32x2 along the
    // reduction dimension (p for stage1, r for stage2).
    unsigned long long w1p[16], w2p[16];
    {
        const float4* p1 = (const float4*)(w1 + (size_t)tid * 32);
#pragma unroll
        for (int i = 0; i < 8; i++) {
            float4 f = p1[i];
            w1p[2*i+0] = pk2(f.x, f.y);
            w1p[2*i+1] = pk2(f.z, f.w);
        }
        const float4* p2 = (const float4*)(w2 + (size_t)(tid & 7) * 1024 + (size_t)(tid >> 3) * 32);
#pragma unroll
        for (int i = 0; i < 8; i++) {
            float4 f = p2[i];
            w2p[2*i+0] = pk2(f.x, f.y);
            w2p[2*i+1] = pk2(f.z, f.w);
        }
    }
    const unsigned long long brp = pk2(bias[tid], 0.f);

    const int t  = tid >> 5;         // token-in-round 0..7
    const int q2 = tid & 31;         // float4 quad 0..31 (handles q2, q2+32)
    const int tokBlock = blockIdx.x * 32;            // 32 tokens per block

    const int kbase = tid & 0xE0;                    // stage1 input block base
    const int widx  = (tid & 7) * 36 + (tid >> 3);   // transposed o1 slot
    const int lbase = (tid & 7) * 36;                // stage2 input row base

    // ---- Prefetch round 0: two coalesced float4 per thread (one token row
    // is covered by 32 threads x 2 quads)
    const float4* r0p = (const float4*)(g_s1 + (size_t)(tokBlock + t) * C_DIM);
    float4 pf0 = __ldcs(&r0p[q2]);
    float4 pf1 = __ldcs(&r0p[q2 + 32]);

#pragma unroll 1
    for (int r = 0; r < 4; r++) {
        const int buf  = r & 1;
        const int tok0 = tokBlock + r * 8;

        // ---- Stage prefetched tile to smem; issue next round's prefetch
        ((float4*)sv[buf][t])[q2]      = pf0;
        ((float4*)sv[buf][t])[q2 + 32] = pf1;
        if (r < 3) {
            const float4* np = (const float4*)(g_s1 + (size_t)(tok0 + 8 + t) * C_DIM);
            pf0 = __ldcs(&np[q2]);
            pf1 = __ldcs(&np[q2 + 32]);
        }

        __syncthreads();   // sv[buf] visible; C(r-1) done reading so1

        // ---- Phase B: stage1, f32x2 along p. o1[k*32+q] = sum_p w1[k,q,p]*v
#pragma unroll
        for (int tt = 0; tt < 8; tt++) {
            const ulonglong2* vp = (const ulonglong2*)(&sv[buf][tt][kbase]);
            unsigned long long acc = 0ull;
#pragma unroll
            for (int p = 0; p < 8; p++) {
                ulonglong2 f = vp[p];          // LDS.128 broadcast, pair-aliased
                ffma2(acc, w1p[2*p+0], f.x);
                ffma2(acc, w1p[2*p+1], f.y);
            }
            so1[tt][widx] = hsum2(acc);   // transposed: c=tid -> (l=c&7, r=c>>3)
        }
        __syncthreads();

        // ---- Phase C: stage2 + bias, f32x2 along r; write f32 t + bf16 shadow
#pragma unroll
        for (int tt = 0; tt < 8; tt++) {
            const ulonglong2* op = (const ulonglong2*)(&so1[tt][lbase]);
            unsigned long long acc = brp;
#pragma unroll
            for (int p = 0; p < 8; p++) {
                ulonglong2 f = op[p];
                ffma2(acc, w2p[2*p+0], f.x);
                ffma2(acc, w2p[2*p+1], f.y);
            }
            const float r2 = hsum2(acc);
            const size_t oi = (size_t)(tok0 + tt) * C_DIM + tid;
            __stcs(&g_t[oi], r2);                      // read-once stream
            g_th[oi] = __float2bfloat16_rn(r2);        // keep resident (gathered)
        }
        // no trailing barrier: next round's sv store targets the other buffer,
        // and barrier1 of the next round protects so1 against its next writer.
    }
}

// ---------------------------------------------------------------------------
// Kernel 2: rectify2 on t + rf. Warp-per-token, barrier-free, BATCHED bf16
// gathers (8 independent LDG.128 in flight before any FMA).
// ---------------------------------------------------------------------------
__global__ void __launch_bounds__(256) k2_rect_add(
        const float* __restrict__ rf,
        const int*   __restrict__ idx,
        float*       __restrict__ out) {
    const int lane = threadIdx.x & 31;
    const int warp = threadIdx.x >> 5;
    const int tok  = blockIdx.x * 8 + warp;     // grid = TOK_TOTAL/8
    const int b    = tok >> 13;
    const __nv_bfloat16* tb = g_th + ((size_t)b << 13) * C_DIM;

    float wv = 0.f; int iv = 0;
    if (lane < 8) {
        wv = g_w[(size_t)tok * 8 + lane];
        iv = idx[(size_t)tok * 8 + lane];
    }
    float wks[8]; const __nv_bfloat16* nps[8];
#pragma unroll
    for (int k = 0; k < 8; k++) {
        wks[k] = __shfl_sync(0xFFFFFFFFu, wv, k);
        nps[k] = tb + (size_t)__shfl_sync(0xFFFFFFFFu, iv, k) * C_DIM;
    }

    // batch all independent loads first
    const float4* trow = (const float4*)(g_t + (size_t)tok * C_DIM);
    float4 s0 = __ldcs(&trow[2*lane]), s1 = __ldcs(&trow[2*lane + 1]);
    const float4* rrow = (const float4*)(rf + (size_t)tok * C_DIM);
    float4 r0 = __ldcs(&rrow[2*lane]), r1 = __ldcs(&rrow[2*lane + 1]);
    uint4 nv[8];
#pragma unroll
    for (int k = 0; k < 8; k++) nv[k] = ((const uint4*)nps[k])[lane];

    float4 a0 = make_float4(OME_W*s0.x + r0.x, OME_W*s0.y + r0.y,
                            OME_W*s0.z + r0.z, OME_W*s0.w + r0.w);
    float4 a1 = make_float4(OME_W*s1.x + r1.x, OME_W*s1.y + r1.y,
                            OME_W*s1.z + r1.z, OME_W*s1.w + r1.w);
#pragma unroll
    for (int k = 0; k < 8; k++) {
        float wk = wks[k]; uint4 n = nv[k];
        a0.x = fmaf(wk, bf_lo(n.x), a0.x);  a0.y = fmaf(wk, bf_hi(n.x), a0.y);
        a0.z = fmaf(wk, bf_lo(n.y), a0.z);  a0.w = fmaf(wk, bf_hi(n.y), a0.w);
        a1.x = fmaf(wk, bf_lo(n.z), a1.x);  a1.y = fmaf(wk, bf_hi(n.z), a1.y);
        a1.z = fmaf(wk, bf_lo(n.w), a1.z);  a1.w = fmaf(wk, bf_hi(n.w), a1.w);
    }

    float4* orow = (float4*)(out + (size_t)tok * C_DIM);
    __stcs(&orow[2*lane],     a0);
    __stcs(&orow[2*lane + 1], a1);
}

// ---------------------------------------------------------------------------
extern "C" void kernel_launch(void* const* d_in, const int* in_sizes, int n_in,
                              void* d_out, int out_size) {
    const float* x    = (const float*)d_in[0];
    const float* dist = (const float*)d_in[1];
    const int*   idx  = (const int*)  d_in[2];
    const float* rf   = (const float*)d_in[3];
    const float* w1   = (const float*)d_in[4];
    const float* w2   = (const float*)d_in[5];
    const float* bias = (const float*)d_in[6];
    float* out = (float*)d_out;

    prep_k<<<256 + (TOK_TOTAL * C_DIM / 4) / 256, 256>>>(dist, x);
    rect1_k<<<TOK_TOTAL / 8, 256>>>(x, idx);
    monarch_k<<<TOK_TOTAL / 32, 256>>>(w1, w2, bias);
    k2_rect_add<<<TOK_TOTAL / 8, 256>>>(rf, idx, out);
}